// round 1
// baseline (speedup 1.0000x reference)
#include <cuda_runtime.h>
#include <math.h>

// Shapes (fixed): B=64, S=512, H=1024, M=26, E=676
// Inputs: 0 seq f32 (64,512,1024), 1 proof_offsets i32 (64,25), 2 node_labels i32,
// 3 edge_labels i32, 4 W_naf, 5 b_naf, 6 W_cd, 7 b_cd, 8 W_co, 9 b_co,
// 10 W_nd, 11 b_nd, 12 W_no, 13 b_no, 14 W_ed (3072,1024), 15 b_ed, 16 W_eo, 17 b_eo
// Output: logits(64,2) ++ node_logits(64,26,2) ++ edge_logits(64,676,2)  = 89984 f32

// ---------------- scratch (static device globals; no allocation) ----------------
__device__ float g_Wcat2[1024 * 2048];   // [W_naf | W_cd]
__device__ float g_bcat2[2048];
__device__ float g_Wcat3[1024 * 3072];   // [W_nd | W1+W3 | W2-W3]
__device__ float g_bcat3[3072];          // [b_nd | b_ed  | 0]
__device__ float g_node[64 * 26 * 1024]; // node_full
__device__ float g_C2[64 * 2048];        // [naf | tanh(cls@W_cd+b_cd)]
__device__ float g_Cbig[1664 * 3072];    // [T_nd | U | V]
__device__ int   g_count[64];

// ---------------- K0: weight concat / fold of W_ed ----------------
__global__ void prep_kernel(const float* __restrict__ W_naf, const float* __restrict__ b_naf,
                            const float* __restrict__ W_cd,  const float* __restrict__ b_cd,
                            const float* __restrict__ W_nd,  const float* __restrict__ b_nd,
                            const float* __restrict__ W_ed,  const float* __restrict__ b_ed)
{
    long gid = blockIdx.x * (long)blockDim.x + threadIdx.x;
    long gsz = gridDim.x * (long)blockDim.x;
    for (long t = gid; t < 1024L * 2048; t += gsz) {
        int k = (int)(t >> 11), n = (int)(t & 2047);
        g_Wcat2[t] = (n < 1024) ? W_naf[k * 1024 + n] : W_cd[k * 1024 + (n - 1024)];
    }
    for (long t = gid; t < 1024L * 3072; t += gsz) {
        int k = (int)(t / 3072), n = (int)(t - (long)k * 3072);
        float v;
        if (n < 1024) {
            v = W_nd[k * 1024 + n];
        } else if (n < 2048) {
            int c = n - 1024;
            v = W_ed[k * 1024 + c] + W_ed[(2048 + k) * 1024 + c];      // nj coeff: W1+W3
        } else {
            int c = n - 2048;
            v = W_ed[(1024 + k) * 1024 + c] - W_ed[(2048 + k) * 1024 + c]; // ni coeff: W2-W3
        }
        g_Wcat3[t] = v;
    }
    for (long t = gid; t < 2048; t += gsz)
        g_bcat2[t] = (t < 1024) ? b_naf[t] : b_cd[t - 1024];
    for (long t = gid; t < 3072; t += gsz)
        g_bcat3[t] = (t < 1024) ? b_nd[t] : ((t < 2048) ? b_ed[t - 1024] : 0.0f);
}

// ---------------- K1: segment means -> node_full, plus count ----------------
// grid (64, 26), 256 threads; thread handles 4 contiguous cols (float4)
__global__ void seg_kernel(const float* __restrict__ seq, const int* __restrict__ off)
{
    int b = blockIdx.x, m = blockIdx.y;
    __shared__ int soff[25];
    int tid = threadIdx.x;
    if (tid < 25) soff[tid] = off[b * 25 + tid];
    __syncthreads();

    int c = 0;
#pragma unroll
    for (int q = 0; q < 25; q++) c += (soff[q] > 0);
    if (m == 0 && tid == 0) g_count[b] = c;

    float* dst = g_node + ((long)b * 26 + m) * 1024 + tid * 4;
    if (m >= c) {                     // invalid segments + appended zero row
        float4 z = {0.f, 0.f, 0.f, 0.f};
        *(float4*)dst = z;
        return;
    }
    int e  = soff[m];
    int s0 = (m ? soff[m - 1] : 0) + 1;   // sum over rows s0..e (inclusive)
    int len = e - s0 + 1;
    const float* p = seq + ((long)b * 512 + s0) * 1024 + tid * 4;
    float4 acc = {0.f, 0.f, 0.f, 0.f};
#pragma unroll 4
    for (int s = 0; s < len; s++) {
        float4 v = *(const float4*)(p + (long)s * 1024);
        acc.x += v.x; acc.y += v.y; acc.z += v.z; acc.w += v.w;
    }
    float inv = 1.0f / (float)len;
    float4 r = {acc.x * inv, acc.y * inv, acc.z * inv, acc.w * inv};
    *(float4*)dst = r;
}

// ---------------- SGEMM: C = X(M x 1024) @ W(1024 x N) + bias, optional tanh on col range
// BM=64, BN=128, BK=16, 256 threads, 4x8 microtile. M, N multiples of tile sizes.
#define BM 64
#define BN 128
#define BKK 16
__global__ __launch_bounds__(256) void sgemm_kernel(
    const float* __restrict__ X, long lda,
    const float* __restrict__ W, int N,
    const float* __restrict__ bias,
    float* __restrict__ C, int ldc,
    int tanh_lo, int tanh_hi)
{
    __shared__ float As[BKK][BM];
    __shared__ float Bs[BKK][BN];
    int m0 = blockIdx.x * BM, n0 = blockIdx.y * BN;
    int tid = threadIdx.x;
    int arow = tid >> 2, akq = (tid & 3) << 2;   // A tile: 64 rows x 16 k, float4 per thread
    int ty = tid >> 4, tx = tid & 15;            // 16x16 thread grid, 4x8 microtile
    const float* Xp = X + (long)(m0 + arow) * lda + akq;

    float acc[4][8];
#pragma unroll
    for (int i = 0; i < 4; i++)
#pragma unroll
        for (int j = 0; j < 8; j++) acc[i][j] = 0.f;

    for (int k0 = 0; k0 < 1024; k0 += BKK) {
        float4 av = *(const float4*)(Xp + k0);
        As[akq + 0][arow] = av.x;
        As[akq + 1][arow] = av.y;
        As[akq + 2][arow] = av.z;
        As[akq + 3][arow] = av.w;
#pragma unroll
        for (int e2 = 0; e2 < 2; e2++) {
            int idx = tid + e2 * 256;
            int kk = idx >> 5, c4 = (idx & 31) << 2;
            *(float4*)&Bs[kk][c4] = *(const float4*)(W + (long)(k0 + kk) * N + n0 + c4);
        }
        __syncthreads();
#pragma unroll
        for (int kk = 0; kk < BKK; kk++) {
            float a[4], bb[8];
            *(float4*)a        = *(const float4*)&As[kk][ty << 2];
            *(float4*)bb       = *(const float4*)&Bs[kk][tx << 3];
            *(float4*)(bb + 4) = *(const float4*)&Bs[kk][(tx << 3) + 4];
#pragma unroll
            for (int i = 0; i < 4; i++)
#pragma unroll
                for (int j = 0; j < 8; j++)
                    acc[i][j] = fmaf(a[i], bb[j], acc[i][j]);
        }
        __syncthreads();
    }

    float bv[8];
#pragma unroll
    for (int j = 0; j < 8; j++) bv[j] = bias ? bias[n0 + (tx << 3) + j] : 0.f;
    bool do_tanh = (n0 >= tanh_lo) && (n0 < tanh_hi);   // uniform per 128-col block
#pragma unroll
    for (int i = 0; i < 4; i++) {
        int row = m0 + (ty << 2) + i;
        float* cp = C + (long)row * ldc + n0 + (tx << 3);
#pragma unroll
        for (int j = 0; j < 8; j++) {
            float v = acc[i][j] + bv[j];
            if (do_tanh) v = tanhf(v);
            cp[j] = v;
        }
    }
}

// ---------------- K3: node_full[b, count[b], :] += naf[b, :] ----------------
__global__ void scatter_naf_kernel()
{
    int b = blockIdx.x, tid = threadIdx.x;   // 256 threads x float4
    int c = g_count[b];
    float* dst = g_node + ((long)b * 26 + c) * 1024 + tid * 4;
    const float* naf = g_C2 + (long)b * 2048 + tid * 4;
    float4 d = *(float4*)dst;
    float4 n = *(const float4*)naf;
    d.x += n.x; d.y += n.y; d.z += n.z; d.w += n.w;
    *(float4*)dst = d;
}

// ---------------- K5/K6: logits + node_logits (block-per-row dot with 2 outputs) ----------------
__global__ void head_kernel(const float* __restrict__ W_co, const float* __restrict__ b_co,
                            const float* __restrict__ W_no, const float* __restrict__ b_no,
                            float* __restrict__ out)
{
    int blk = blockIdx.x, tid = threadIdx.x;   // 128 threads
    const float* x; const float* Wv; const float* bs; float* op;
    if (blk < 64) {
        x  = g_C2 + (long)blk * 2048 + 1024;   // tanh(cls@W_cd+b_cd)
        Wv = W_co; bs = b_co; op = out + blk * 2;
    } else {
        int r = blk - 64;
        x  = g_Cbig + (long)r * 3072;          // T_nd
        Wv = W_no; bs = b_no; op = out + 128 + r * 2;
    }
    float xs[8], ws[16];
    {
        const float4* xv = (const float4*)(x + tid * 8);
        *(float4*)xs       = xv[0];
        *(float4*)(xs + 4) = xv[1];
        const float4* wv = (const float4*)(Wv + tid * 16);
#pragma unroll
        for (int q = 0; q < 4; q++) *(float4*)(ws + q * 4) = wv[q];
    }
    float a0 = 0.f, a1 = 0.f;
#pragma unroll
    for (int hh = 0; hh < 8; hh++) {
        a0 = fmaf(xs[hh], ws[2 * hh], a0);
        a1 = fmaf(xs[hh], ws[2 * hh + 1], a1);
    }
#pragma unroll
    for (int o = 16; o > 0; o >>= 1) {
        a0 += __shfl_down_sync(0xffffffffu, a0, o);
        a1 += __shfl_down_sync(0xffffffffu, a1, o);
    }
    __shared__ float s0[4], s1[4];
    int wid = tid >> 5, lane = tid & 31;
    if (lane == 0) { s0[wid] = a0; s1[wid] = a1; }
    __syncthreads();
    if (tid == 0) {
        op[0] = s0[0] + s0[1] + s0[2] + s0[3] + bs[0];
        op[1] = s1[0] + s1[1] + s1[2] + s1[3] + bs[1];
    }
}

// ---------------- K7: edge logits ----------------
// block per global edge (64*676); edge_d = U[j] + V[i] (U carries b_ed), invalid -> b_ed
__global__ void edge_kernel(const float* __restrict__ W_eo, const float* __restrict__ b_eo,
                            const float* __restrict__ b_ed, float* __restrict__ out)
{
    int ke = blockIdx.x;
    int b  = ke / 676;
    int k  = ke - b * 676;
    int n  = g_count[b] + 1;
    int tid = threadIdx.x;   // 128

    float xs[8];
    if (k < n * n) {
        int i = k / n, j = k - i * n;
        const float* U = g_Cbig + ((long)(b * 26 + j)) * 3072 + 1024 + tid * 8;
        const float* V = g_Cbig + ((long)(b * 26 + i)) * 3072 + 2048 + tid * 8;
        float us[8], vs[8];
        *(float4*)us       = ((const float4*)U)[0];
        *(float4*)(us + 4) = ((const float4*)U)[1];
        *(float4*)vs       = ((const float4*)V)[0];
        *(float4*)(vs + 4) = ((const float4*)V)[1];
#pragma unroll
        for (int hh = 0; hh < 8; hh++) xs[hh] = tanhf(us[hh] + vs[hh]);
    } else {
        const float* be = b_ed + tid * 8;
        float bs8[8];
        *(float4*)bs8       = ((const float4*)be)[0];
        *(float4*)(bs8 + 4) = ((const float4*)be)[1];
#pragma unroll
        for (int hh = 0; hh < 8; hh++) xs[hh] = tanhf(bs8[hh]);
    }
    float ws[16];
    {
        const float4* wv = (const float4*)(W_eo + tid * 16);
#pragma unroll
        for (int q = 0; q < 4; q++) *(float4*)(ws + q * 4) = wv[q];
    }
    float a0 = 0.f, a1 = 0.f;
#pragma unroll
    for (int hh = 0; hh < 8; hh++) {
        a0 = fmaf(xs[hh], ws[2 * hh], a0);
        a1 = fmaf(xs[hh], ws[2 * hh + 1], a1);
    }
#pragma unroll
    for (int o = 16; o > 0; o >>= 1) {
        a0 += __shfl_down_sync(0xffffffffu, a0, o);
        a1 += __shfl_down_sync(0xffffffffu, a1, o);
    }
    __shared__ float s0[4], s1[4];
    int wid = tid >> 5, lane = tid & 31;
    if (lane == 0) { s0[wid] = a0; s1[wid] = a1; }
    __syncthreads();
    if (tid == 0) {
        float* op = out + 3456 + (long)ke * 2;
        op[0] = s0[0] + s0[1] + s0[2] + s0[3] + b_eo[0];
        op[1] = s1[0] + s1[1] + s1[2] + s1[3] + b_eo[1];
    }
}

// ---------------- launch ----------------
extern "C" void kernel_launch(void* const* d_in, const int* in_sizes, int n_in,
                              void* d_out, int out_size)
{
    const float* seq   = (const float*)d_in[0];
    const int*   off   = (const int*)d_in[1];
    const float* W_naf = (const float*)d_in[4];
    const float* b_naf = (const float*)d_in[5];
    const float* W_cd  = (const float*)d_in[6];
    const float* b_cd  = (const float*)d_in[7];
    const float* W_co  = (const float*)d_in[8];
    const float* b_co  = (const float*)d_in[9];
    const float* W_nd  = (const float*)d_in[10];
    const float* b_nd  = (const float*)d_in[11];
    const float* W_no  = (const float*)d_in[12];
    const float* b_no  = (const float*)d_in[13];
    const float* W_ed  = (const float*)d_in[14];
    const float* b_ed  = (const float*)d_in[15];
    const float* W_eo  = (const float*)d_in[16];
    const float* b_eo  = (const float*)d_in[17];
    float* out = (float*)d_out;

    float *pWcat2, *pbcat2, *pWcat3, *pbcat3, *pnode, *pC2, *pCbig;
    cudaGetSymbolAddress((void**)&pWcat2, g_Wcat2);
    cudaGetSymbolAddress((void**)&pbcat2, g_bcat2);
    cudaGetSymbolAddress((void**)&pWcat3, g_Wcat3);
    cudaGetSymbolAddress((void**)&pbcat3, g_bcat3);
    cudaGetSymbolAddress((void**)&pnode,  g_node);
    cudaGetSymbolAddress((void**)&pC2,    g_C2);
    cudaGetSymbolAddress((void**)&pCbig,  g_Cbig);

    // K0: weight folding (independent of everything else)
    prep_kernel<<<1024, 256>>>(W_naf, b_naf, W_cd, b_cd, W_nd, b_nd, W_ed, b_ed);
    // K1: segment means + count
    seg_kernel<<<dim3(64, 26), 256>>>(seq, off);
    // G1: cls @ [W_naf | W_cd] -> g_C2 (tanh on cols [1024,2048))
    sgemm_kernel<<<dim3(1, 16), 256>>>(seq, (long)512 * 1024, pWcat2, 2048, pbcat2,
                                       pC2, 2048, 1024, 2048);
    // K3: add naf into node_full at row count[b]
    scatter_naf_kernel<<<64, 256>>>();
    // G2: node_full @ [W_nd | A | B] -> g_Cbig (tanh on cols [0,1024))
    sgemm_kernel<<<dim3(26, 24), 256>>>(pnode, 1024, pWcat3, 3072, pbcat3,
                                        pCbig, 3072, 0, 1024);
    // K5/K6: logits + node_logits
    head_kernel<<<64 + 1664, 128>>>(W_co, b_co, W_no, b_no, out);
    // K7: edge logits
    edge_kernel<<<64 * 676, 128>>>(W_eo, b_eo, b_ed, out);
}

// round 2
// speedup vs baseline: 2.0863x; 2.0863x over previous
#include <cuda_runtime.h>
#include <math.h>
#include <stdint.h>

// Shapes (fixed): B=64, S=512, H=1024, M=26, E=676
// Output: logits(64,2) ++ node_logits(64,26,2) ++ edge_logits(64,676,2) = 89984 f32

// ---------------- scratch (static device globals; no allocation) ----------------
__device__ float g_Wcat2[1024 * 2048];   // [W_naf | W_cd]
__device__ float g_bcat2[2048];
__device__ float g_Wcat3[1024 * 3072];   // [W_nd | W1+W3 | W2-W3]
__device__ float g_bcat3[3072];          // [b_nd | b_ed  | 0]
__device__ float g_node[64 * 26 * 1024]; // node_full
__device__ float g_C2[64 * 2048];        // [naf | tanh(cls@W_cd+b_cd)]
__device__ float g_Cbig[1664 * 3072];    // [T_nd | U | V]
__device__ int   g_count[64];

// ---------------- K0: weight concat / fold of W_ed ----------------
__global__ void prep_kernel(const float* __restrict__ W_naf, const float* __restrict__ b_naf,
                            const float* __restrict__ W_cd,  const float* __restrict__ b_cd,
                            const float* __restrict__ W_nd,  const float* __restrict__ b_nd,
                            const float* __restrict__ W_ed,  const float* __restrict__ b_ed)
{
    long gid = blockIdx.x * (long)blockDim.x + threadIdx.x;
    long gsz = gridDim.x * (long)blockDim.x;
    for (long t = gid; t < 1024L * 2048; t += gsz) {
        int k = (int)(t >> 11), n = (int)(t & 2047);
        g_Wcat2[t] = (n < 1024) ? W_naf[k * 1024 + n] : W_cd[k * 1024 + (n - 1024)];
    }
    for (long t = gid; t < 1024L * 3072; t += gsz) {
        int k = (int)(t / 3072), n = (int)(t - (long)k * 3072);
        float v;
        if (n < 1024) {
            v = W_nd[k * 1024 + n];
        } else if (n < 2048) {
            int c = n - 1024;
            v = W_ed[k * 1024 + c] + W_ed[(2048 + k) * 1024 + c];          // nj coeff: W1+W3
        } else {
            int c = n - 2048;
            v = W_ed[(1024 + k) * 1024 + c] - W_ed[(2048 + k) * 1024 + c]; // ni coeff: W2-W3
        }
        g_Wcat3[t] = v;
    }
    for (long t = gid; t < 2048; t += gsz)
        g_bcat2[t] = (t < 1024) ? b_naf[t] : b_cd[t - 1024];
    for (long t = gid; t < 3072; t += gsz)
        g_bcat3[t] = (t < 1024) ? b_nd[t] : ((t < 2048) ? b_ed[t - 1024] : 0.0f);
}

// ---------------- K1: segment means -> node_full, plus count ----------------
__global__ void seg_kernel(const float* __restrict__ seq, const int* __restrict__ off)
{
    int b = blockIdx.x, m = blockIdx.y;
    __shared__ int soff[25];
    int tid = threadIdx.x;
    if (tid < 25) soff[tid] = off[b * 25 + tid];
    __syncthreads();

    int c = 0;
#pragma unroll
    for (int q = 0; q < 25; q++) c += (soff[q] > 0);
    if (m == 0 && tid == 0) g_count[b] = c;

    float* dst = g_node + ((long)b * 26 + m) * 1024 + tid * 4;
    if (m >= c) {
        float4 z = {0.f, 0.f, 0.f, 0.f};
        *(float4*)dst = z;
        return;
    }
    int e  = soff[m];
    int s0 = (m ? soff[m - 1] : 0) + 1;
    int len = e - s0 + 1;
    const float* p = seq + ((long)b * 512 + s0) * 1024 + tid * 4;
    float4 acc = {0.f, 0.f, 0.f, 0.f};
#pragma unroll 4
    for (int s = 0; s < len; s++) {
        float4 v = *(const float4*)(p + (long)s * 1024);
        acc.x += v.x; acc.y += v.y; acc.z += v.z; acc.w += v.w;
    }
    float inv = 1.0f / (float)len;
    float4 r = {acc.x * inv, acc.y * inv, acc.z * inv, acc.w * inv};
    *(float4*)dst = r;
}

// ---------------- tf32 tensor-core GEMM ----------------
// C[M,N] = X[M,1024] @ W[1024,N] + bias, optional tanh on column range.
// Block tile 128x128x16, 256 threads (8 warps, 2x4 -> warp tile 64x32).
// mma.sync.m16n8k8.tf32. Smem padded for conflict-free fragment reads.
__device__ __forceinline__ float tf32r(float x) {
    float y;
    asm("cvt.rna.tf32.f32 %0, %1;" : "=f"(y) : "f"(x));
    return y;
}

__global__ __launch_bounds__(256) void mma_gemm_kernel(
    const float* __restrict__ X, long lda, int Mrows,
    const float* __restrict__ W, int N,
    const float* __restrict__ bias,
    float* __restrict__ C, int ldc,
    int tanh_lo, int tanh_hi)
{
    __shared__ float As[128][20];   // [m][k], stride 20 -> conflict-free frag reads
    __shared__ float Bs[16][136];   // [k][n], stride 136 -> conflict-free frag reads

    int tid  = threadIdx.x;
    int lane = tid & 31;
    int w    = tid >> 5;
    int wm   = (w & 1) * 64;        // warp row offset in block tile
    int wn   = (w >> 1) * 32;       // warp col offset
    int gq   = lane >> 2;           // groupID
    int tg   = lane & 3;            // threadID in group

    int m0 = blockIdx.x * 128, n0 = blockIdx.y * 128;

    float acc[4][4][4];
#pragma unroll
    for (int mt = 0; mt < 4; mt++)
#pragma unroll
        for (int nt = 0; nt < 4; nt++)
#pragma unroll
            for (int cfi = 0; cfi < 4; cfi++) acc[mt][nt][cfi] = 0.f;

    // global->smem indexing
    int arow = tid >> 1;                 // 0..127
    int acol = (tid & 1) << 3;           // 0 or 8
    bool avalid = (m0 + arow) < Mrows;
    const float* Ap = X + (long)(m0 + arow) * lda + acol;

    for (int k0 = 0; k0 < 1024; k0 += 16) {
        // --- load A tile (128x16), convert to tf32 ---
        float4 av0 = make_float4(0.f, 0.f, 0.f, 0.f), av1 = av0;
        if (avalid) {
            av0 = *(const float4*)(Ap + k0);
            av1 = *(const float4*)(Ap + k0 + 4);
        }
        av0.x = tf32r(av0.x); av0.y = tf32r(av0.y); av0.z = tf32r(av0.z); av0.w = tf32r(av0.w);
        av1.x = tf32r(av1.x); av1.y = tf32r(av1.y); av1.z = tf32r(av1.z); av1.w = tf32r(av1.w);
        *(float4*)&As[arow][acol]     = av0;
        *(float4*)&As[arow][acol + 4] = av1;

        // --- load B tile (16x128), convert to tf32 ---
#pragma unroll
        for (int e2 = 0; e2 < 2; e2++) {
            int f  = tid + e2 * 256;
            int br = f >> 5;
            int bc = (f & 31) << 2;
            float4 bv = *(const float4*)(W + (long)(k0 + br) * N + n0 + bc);
            bv.x = tf32r(bv.x); bv.y = tf32r(bv.y); bv.z = tf32r(bv.z); bv.w = tf32r(bv.w);
            *(float4*)&Bs[br][bc] = bv;
        }
        __syncthreads();

#pragma unroll
        for (int kk = 0; kk < 16; kk += 8) {
            uint32_t af[4][4];
#pragma unroll
            for (int mt = 0; mt < 4; mt++) {
                int r = wm + mt * 16 + gq;
                int c = kk + tg;
                af[mt][0] = __float_as_uint(As[r][c]);
                af[mt][1] = __float_as_uint(As[r + 8][c]);
                af[mt][2] = __float_as_uint(As[r][c + 4]);
                af[mt][3] = __float_as_uint(As[r + 8][c + 4]);
            }
            uint32_t bf[4][2];
#pragma unroll
            for (int nt = 0; nt < 4; nt++) {
                int cn = wn + nt * 8 + gq;
                bf[nt][0] = __float_as_uint(Bs[kk + tg][cn]);
                bf[nt][1] = __float_as_uint(Bs[kk + tg + 4][cn]);
            }
#pragma unroll
            for (int mt = 0; mt < 4; mt++)
#pragma unroll
                for (int nt = 0; nt < 4; nt++) {
                    asm volatile(
                        "mma.sync.aligned.m16n8k8.row.col.f32.tf32.tf32.f32 "
                        "{%0,%1,%2,%3}, {%4,%5,%6,%7}, {%8,%9}, {%0,%1,%2,%3};"
                        : "+f"(acc[mt][nt][0]), "+f"(acc[mt][nt][1]),
                          "+f"(acc[mt][nt][2]), "+f"(acc[mt][nt][3])
                        : "r"(af[mt][0]), "r"(af[mt][1]), "r"(af[mt][2]), "r"(af[mt][3]),
                          "r"(bf[nt][0]), "r"(bf[nt][1]));
                }
        }
        __syncthreads();
    }

    // --- epilogue: bias + optional tanh, float2 stores ---
    bool do_tanh = (n0 >= tanh_lo) && (n0 < tanh_hi);
#pragma unroll
    for (int nt = 0; nt < 4; nt++) {
        int col = n0 + wn + nt * 8 + 2 * tg;
        float b0v = bias ? bias[col]     : 0.f;
        float b1v = bias ? bias[col + 1] : 0.f;
#pragma unroll
        for (int mt = 0; mt < 4; mt++) {
            int r0 = m0 + wm + mt * 16 + gq;
            float v0 = acc[mt][nt][0] + b0v;
            float v1 = acc[mt][nt][1] + b1v;
            float v2 = acc[mt][nt][2] + b0v;
            float v3 = acc[mt][nt][3] + b1v;
            if (do_tanh) { v0 = tanhf(v0); v1 = tanhf(v1); v2 = tanhf(v2); v3 = tanhf(v3); }
            if (r0 < Mrows) {
                float2 p = {v0, v1};
                *(float2*)(C + (long)r0 * ldc + col) = p;
            }
            if (r0 + 8 < Mrows) {
                float2 p = {v2, v3};
                *(float2*)(C + (long)(r0 + 8) * ldc + col) = p;
            }
        }
    }
}

// ---------------- K3: node_full[b, count[b], :] += naf[b, :] ----------------
__global__ void scatter_naf_kernel()
{
    int b = blockIdx.x, tid = threadIdx.x;
    int c = g_count[b];
    float* dst = g_node + ((long)b * 26 + c) * 1024 + tid * 4;
    const float* naf = g_C2 + (long)b * 2048 + tid * 4;
    float4 d = *(float4*)dst;
    float4 n = *(const float4*)naf;
    d.x += n.x; d.y += n.y; d.z += n.z; d.w += n.w;
    *(float4*)dst = d;
}

// ---------------- K5/K6: logits + node_logits ----------------
__global__ void head_kernel(const float* __restrict__ W_co, const float* __restrict__ b_co,
                            const float* __restrict__ W_no, const float* __restrict__ b_no,
                            float* __restrict__ out)
{
    int blk = blockIdx.x, tid = threadIdx.x;   // 128 threads
    const float* x; const float* Wv; const float* bs; float* op;
    if (blk < 64) {
        x  = g_C2 + (long)blk * 2048 + 1024;
        Wv = W_co; bs = b_co; op = out + blk * 2;
    } else {
        int r = blk - 64;
        x  = g_Cbig + (long)r * 3072;
        Wv = W_no; bs = b_no; op = out + 128 + r * 2;
    }
    float xs[8], ws[16];
    {
        const float4* xv = (const float4*)(x + tid * 8);
        *(float4*)xs       = xv[0];
        *(float4*)(xs + 4) = xv[1];
        const float4* wv = (const float4*)(Wv + tid * 16);
#pragma unroll
        for (int q = 0; q < 4; q++) *(float4*)(ws + q * 4) = wv[q];
    }
    float a0 = 0.f, a1 = 0.f;
#pragma unroll
    for (int hh = 0; hh < 8; hh++) {
        a0 = fmaf(xs[hh], ws[2 * hh], a0);
        a1 = fmaf(xs[hh], ws[2 * hh + 1], a1);
    }
#pragma unroll
    for (int o = 16; o > 0; o >>= 1) {
        a0 += __shfl_down_sync(0xffffffffu, a0, o);
        a1 += __shfl_down_sync(0xffffffffu, a1, o);
    }
    __shared__ float s0[4], s1[4];
    int wid = tid >> 5, lane = tid & 31;
    if (lane == 0) { s0[wid] = a0; s1[wid] = a1; }
    __syncthreads();
    if (tid == 0) {
        op[0] = s0[0] + s0[1] + s0[2] + s0[3] + bs[0];
        op[1] = s1[0] + s1[1] + s1[2] + s1[3] + bs[1];
    }
}

// ---------------- K7: edge logits ----------------
__global__ void edge_kernel(const float* __restrict__ W_eo, const float* __restrict__ b_eo,
                            const float* __restrict__ b_ed, float* __restrict__ out)
{
    int ke = blockIdx.x;
    int b  = ke / 676;
    int k  = ke - b * 676;
    int n  = g_count[b] + 1;
    int tid = threadIdx.x;   // 128

    float xs[8];
    if (k < n * n) {
        int i = k / n, j = k - i * n;
        const float* U = g_Cbig + ((long)(b * 26 + j)) * 3072 + 1024 + tid * 8;
        const float* V = g_Cbig + ((long)(b * 26 + i)) * 3072 + 2048 + tid * 8;
        float us[8], vs[8];
        *(float4*)us       = ((const float4*)U)[0];
        *(float4*)(us + 4) = ((const float4*)U)[1];
        *(float4*)vs       = ((const float4*)V)[0];
        *(float4*)(vs + 4) = ((const float4*)V)[1];
#pragma unroll
        for (int hh = 0; hh < 8; hh++) xs[hh] = tanhf(us[hh] + vs[hh]);
    } else {
        const float* be = b_ed + tid * 8;
        float bs8[8];
        *(float4*)bs8       = ((const float4*)be)[0];
        *(float4*)(bs8 + 4) = ((const float4*)be)[1];
#pragma unroll
        for (int hh = 0; hh < 8; hh++) xs[hh] = tanhf(bs8[hh]);
    }
    float ws[16];
    {
        const float4* wv = (const float4*)(W_eo + tid * 16);
#pragma unroll
        for (int q = 0; q < 4; q++) *(float4*)(ws + q * 4) = wv[q];
    }
    float a0 = 0.f, a1 = 0.f;
#pragma unroll
    for (int hh = 0; hh < 8; hh++) {
        a0 = fmaf(xs[hh], ws[2 * hh], a0);
        a1 = fmaf(xs[hh], ws[2 * hh + 1], a1);
    }
#pragma unroll
    for (int o = 16; o > 0; o >>= 1) {
        a0 += __shfl_down_sync(0xffffffffu, a0, o);
        a1 += __shfl_down_sync(0xffffffffu, a1, o);
    }
    __shared__ float s0[4], s1[4];
    int wid = tid >> 5, lane = tid & 31;
    if (lane == 0) { s0[wid] = a0; s1[wid] = a1; }
    __syncthreads();
    if (tid == 0) {
        float* op = out + 3456 + (long)ke * 2;
        op[0] = s0[0] + s0[1] + s0[2] + s0[3] + b_eo[0];
        op[1] = s1[0] + s1[1] + s1[2] + s1[3] + b_eo[1];
    }
}

// ---------------- launch ----------------
extern "C" void kernel_launch(void* const* d_in, const int* in_sizes, int n_in,
                              void* d_out, int out_size)
{
    const float* seq   = (const float*)d_in[0];
    const int*   off   = (const int*)d_in[1];
    const float* W_naf = (const float*)d_in[4];
    const float* b_naf = (const float*)d_in[5];
    const float* W_cd  = (const float*)d_in[6];
    const float* b_cd  = (const float*)d_in[7];
    const float* W_co  = (const float*)d_in[8];
    const float* b_co  = (const float*)d_in[9];
    const float* W_nd  = (const float*)d_in[10];
    const float* b_nd  = (const float*)d_in[11];
    const float* W_no  = (const float*)d_in[12];
    const float* b_no  = (const float*)d_in[13];
    const float* W_ed  = (const float*)d_in[14];
    const float* b_ed  = (const float*)d_in[15];
    const float* W_eo  = (const float*)d_in[16];
    const float* b_eo  = (const float*)d_in[17];
    float* out = (float*)d_out;

    float *pWcat2, *pbcat2, *pWcat3, *pbcat3, *pnode, *pC2, *pCbig;
    cudaGetSymbolAddress((void**)&pWcat2, g_Wcat2);
    cudaGetSymbolAddress((void**)&pbcat2, g_bcat2);
    cudaGetSymbolAddress((void**)&pWcat3, g_Wcat3);
    cudaGetSymbolAddress((void**)&pbcat3, g_bcat3);
    cudaGetSymbolAddress((void**)&pnode,  g_node);
    cudaGetSymbolAddress((void**)&pC2,    g_C2);
    cudaGetSymbolAddress((void**)&pCbig,  g_Cbig);

    // K0: weight folding
    prep_kernel<<<1024, 256>>>(W_naf, b_naf, W_cd, b_cd, W_nd, b_nd, W_ed, b_ed);
    // K1: segment means + count
    seg_kernel<<<dim3(64, 26), 256>>>(seq, off);
    // G1: cls @ [W_naf | W_cd] -> g_C2 (tanh on cols [1024,2048))
    mma_gemm_kernel<<<dim3(1, 16), 256>>>(seq, (long)512 * 1024, 64, pWcat2, 2048, pbcat2,
                                          pC2, 2048, 1024, 2048);
    // K3: add naf into node_full at row count[b]
    scatter_naf_kernel<<<64, 256>>>();
    // G2: node_full @ [W_nd | A | B] -> g_Cbig (tanh on cols [0,1024))
    mma_gemm_kernel<<<dim3(13, 24), 256>>>(pnode, 1024, 1664, pWcat3, 3072, pbcat3,
                                           pCbig, 3072, 0, 1024);
    // K5/K6: logits + node_logits
    head_kernel<<<64 + 1664, 128>>>(W_co, b_co, W_no, b_no, out);
    // K7: edge logits
    edge_kernel<<<64 * 676, 128>>>(W_eo, b_eo, b_ed, out);
}

// round 4
// speedup vs baseline: 2.7406x; 1.3136x over previous
#include <cuda_runtime.h>
#include <cuda_fp16.h>
#include <math.h>
#include <stdint.h>

// Shapes (fixed): B=64, S=512, H=1024, M=26, E=676
// Output: logits(64,2) ++ node_logits(64,26,2) ++ edge_logits(64,676,2) = 89984 f32
//
// GEMMs via legacy mma.m16n8k16.f16 with 3-term hi/lo split (fp32-class accuracy):
//  G1: cls(64x1024)   @ [W_naf|W_cd](1024x2048)          -> g_C2
//  G2: nodeC(Rx1024)  @ [W_nd|W1+W3|W2-W3](1024x3072)    -> g_Cbig (compact rows)
// Block tile 128x128, K slabs of 32, pre-fragmented packs, cp.async double buffer.

// ---------------- scratch ----------------
__device__ float g_bcat2[2048];
__device__ float g_bcat3[3072];
__device__ float g_node[64 * 26 * 1024];
__device__ float g_C2[64 * 2048];
__device__ float g_Cbig[1664 * 3072];    // compact rows used: [T_nd | U | V]
__device__ int   g_count[64];
__device__ int   g_pref[64];
__device__ int   g_rowmap[1664];
__device__ int   g_R;
__device__ int   g_M1 = 64;
__device__ float g_zlog[2];

// pre-fragmented fp16 hi/lo packs (slab = 128rows x 32k, hi 8KB + lo 8KB = 8192 halves)
__device__ __align__(16) __half g_ApackN[13 * 32 * 8192];
__device__ __align__(16) __half g_ApackC[32 * 8192];
__device__ __align__(16) __half g_BpackN[24 * 32 * 8192];
__device__ __align__(16) __half g_BpackC[16 * 32 * 8192];

// ---------------- helpers ----------------
__device__ __forceinline__ uint32_t smem_u32(const void* p) {
    uint32_t a;
    asm("{ .reg .u64 t; cvta.to.shared.u64 t, %1; cvt.u32.u64 %0, t; }" : "=r"(a) : "l"(p));
    return a;
}
#define CP16(dst, src) asm volatile("cp.async.cg.shared.global [%0], [%1], 16;" :: "r"(dst), "l"(src) : "memory")
#define CP_COMMIT()    asm volatile("cp.async.commit_group;" ::: "memory")
#define CP_WAIT1()     asm volatile("cp.async.wait_group 1;" ::: "memory")
#define CP_WAIT0()     asm volatile("cp.async.wait_group 0;" ::: "memory")

#define MMA16(d, a, bb0, bb1) \
    asm volatile("mma.sync.aligned.m16n8k16.row.col.f32.f16.f16.f32 " \
                 "{%0,%1,%2,%3}, {%4,%5,%6,%7}, {%8,%9}, {%0,%1,%2,%3};" \
                 : "+f"((d)[0]), "+f"((d)[1]), "+f"((d)[2]), "+f"((d)[3]) \
                 : "r"((a).x), "r"((a).y), "r"((a).z), "r"((a).w), "r"(bb0), "r"(bb1))

// hi/lo fp16 split of a float pair -> packed half2 regs
__device__ __forceinline__ void hl2(float a, float b, uint32_t& h, uint32_t& l) {
    __half ha = __float2half_rn(a), hb = __float2half_rn(b);
    __half la = __float2half_rn(a - __half2float(ha));
    __half lb = __float2half_rn(b - __half2float(hb));
    __half2 H = __halves2half2(ha, hb), L = __halves2half2(la, lb);
    h = *(uint32_t*)&H; l = *(uint32_t*)&L;
}

// ---------------- K0: biases ----------------
__global__ void prep_bias_kernel(const float* __restrict__ b_naf, const float* __restrict__ b_cd,
                                 const float* __restrict__ b_nd,  const float* __restrict__ b_ed)
{
    int t = blockIdx.x * blockDim.x + threadIdx.x;
    if (t < 2048) g_bcat2[t] = (t < 1024) ? b_naf[t] : b_cd[t - 1024];
    if (t < 3072) g_bcat3[t] = (t < 1024) ? b_nd[t] : ((t < 2048) ? b_ed[t - 1024] : 0.0f);
}

// zero-row node logits: tanh(b_nd) @ W_no + b_no
__global__ void zlog_kernel(const float* __restrict__ b_nd, const float* __restrict__ W_no,
                            const float* __restrict__ b_no)
{
    int tid = threadIdx.x;  // 128
    float a0 = 0.f, a1 = 0.f;
#pragma unroll
    for (int hh = 0; hh < 8; hh++) {
        float x = tanhf(b_nd[tid * 8 + hh]);
        a0 = fmaf(x, W_no[(tid * 8 + hh) * 2],     a0);
        a1 = fmaf(x, W_no[(tid * 8 + hh) * 2 + 1], a1);
    }
#pragma unroll
    for (int o = 16; o > 0; o >>= 1) {
        a0 += __shfl_down_sync(0xffffffffu, a0, o);
        a1 += __shfl_down_sync(0xffffffffu, a1, o);
    }
    __shared__ float s0[4], s1[4];
    int wid = tid >> 5, lane = tid & 31;
    if (lane == 0) { s0[wid] = a0; s1[wid] = a1; }
    __syncthreads();
    if (tid == 0) {
        g_zlog[0] = s0[0] + s0[1] + s0[2] + s0[3] + b_no[0];
        g_zlog[1] = s1[0] + s1[1] + s1[2] + s1[3] + b_no[1];
    }
}

// ---------------- K1: segment means + counts ----------------
__global__ void seg_kernel(const float* __restrict__ seq, const int* __restrict__ off)
{
    int b = blockIdx.x, m = blockIdx.y;
    __shared__ int soff[25];
    int tid = threadIdx.x;
    if (tid < 25) soff[tid] = off[b * 25 + tid];
    __syncthreads();
    int c = 0;
#pragma unroll
    for (int q = 0; q < 25; q++) c += (soff[q] > 0);
    if (m == 0 && tid == 0) g_count[b] = c;

    float* dst = g_node + ((size_t)b * 26 + m) * 1024 + tid * 4;
    if (m >= c) { float4 z = {0.f, 0.f, 0.f, 0.f}; *(float4*)dst = z; return; }
    int e  = soff[m];
    int s0 = (m ? soff[m - 1] : 0) + 1;
    int len = e - s0 + 1;
    const float* p = seq + ((size_t)b * 512 + s0) * 1024 + tid * 4;
    float4 acc = {0.f, 0.f, 0.f, 0.f};
#pragma unroll 4
    for (int s = 0; s < len; s++) {
        float4 v = *(const float4*)(p + (size_t)s * 1024);
        acc.x += v.x; acc.y += v.y; acc.z += v.z; acc.w += v.w;
    }
    float inv = 1.0f / (float)len;
    float4 r = {acc.x * inv, acc.y * inv, acc.z * inv, acc.w * inv};
    *(float4*)dst = r;
}

// ---------------- prefix + rowmap ----------------
__global__ void prefix_kernel()
{
    __shared__ int sc[64], sp[64];
    int tid = threadIdx.x;
    if (tid < 64) sc[tid] = g_count[tid];
    __syncthreads();
    if (tid == 0) {
        int p = 0;
        for (int b = 0; b < 64; b++) { sp[b] = p; g_pref[b] = p; p += sc[b] + 1; }
        g_R = p;
    }
    __syncthreads();
    for (int r = tid; r < 1664; r += 256) {
        int b = r / 26, m = r - b * 26;
        if (m <= sc[b]) g_rowmap[sp[b] + m] = r;
    }
}

// ---------------- K3: node_full[b, count[b], :] += naf ----------------
__global__ void scatter_naf_kernel()
{
    int b = blockIdx.x, tid = threadIdx.x;
    int c = g_count[b];
    float* dst = g_node + ((size_t)b * 26 + c) * 1024 + tid * 4;
    const float* naf = g_C2 + (size_t)b * 2048 + tid * 4;
    float4 d = *(float4*)dst;
    float4 n = *(const float4*)naf;
    d.x += n.x; d.y += n.y; d.z += n.z; d.w += n.w;
    *(float4*)dst = d;
}

// ---------------- A packs (fragment order, hi/lo) ----------------
// chunk c: kk16=c>>8, mt16=(c>>5)&7, lane=c&31; 16B = [a0pair,a1pair,a2pair,a3pair]
__global__ void packAnode_kernel()
{
    int mb = blockIdx.x, s = blockIdx.y;
    int R = g_R;
    if (mb * 128 >= R) return;
    __half* tile = g_ApackN + ((size_t)(mb * 32 + s)) * 8192;
    for (int c = threadIdx.x; c < 512; c += 256) {
        int kk16 = c >> 8, mt16 = (c >> 5) & 7, lane = c & 31;
        int gq = lane >> 2, tg = lane & 3;
        int kb = s * 32 + kk16 * 16 + 2 * tg;
        int r0 = mb * 128 + mt16 * 16 + gq, r1 = r0 + 8;
        float x0[4] = {0,0,0,0}, x1[4] = {0,0,0,0};
        if (r0 < R) { const float* p = g_node + (size_t)g_rowmap[r0] * 1024 + kb;
                      x0[0]=p[0]; x0[1]=p[1]; x0[2]=p[8]; x0[3]=p[9]; }
        if (r1 < R) { const float* p = g_node + (size_t)g_rowmap[r1] * 1024 + kb;
                      x1[0]=p[0]; x1[1]=p[1]; x1[2]=p[8]; x1[3]=p[9]; }
        uint4 hi, lo;
        hl2(x0[0], x0[1], hi.x, lo.x);
        hl2(x1[0], x1[1], hi.y, lo.y);
        hl2(x0[2], x0[3], hi.z, lo.z);
        hl2(x1[2], x1[3], hi.w, lo.w);
        uint32_t off = (uint32_t)(kk16 * 8 + mt16) * 512 + lane * 16;
        *(uint4*)((char*)tile + off)        = hi;
        *(uint4*)((char*)tile + 8192 + off) = lo;
    }
}

__global__ void packAcls_kernel(const float* __restrict__ seq)
{
    int s = blockIdx.x;
    __half* tile = g_ApackC + ((size_t)s) * 8192;
    for (int c = threadIdx.x; c < 512; c += 256) {
        int kk16 = c >> 8, mt16 = (c >> 5) & 7, lane = c & 31;
        int gq = lane >> 2, tg = lane & 3;
        int kb = s * 32 + kk16 * 16 + 2 * tg;
        int r0 = mt16 * 16 + gq, r1 = r0 + 8;
        float x0[4] = {0,0,0,0}, x1[4] = {0,0,0,0};
        if (r0 < 64) { const float* p = seq + (size_t)r0 * 524288 + kb;
                       x0[0]=p[0]; x0[1]=p[1]; x0[2]=p[8]; x0[3]=p[9]; }
        if (r1 < 64) { const float* p = seq + (size_t)r1 * 524288 + kb;
                       x1[0]=p[0]; x1[1]=p[1]; x1[2]=p[8]; x1[3]=p[9]; }
        uint4 hi, lo;
        hl2(x0[0], x0[1], hi.x, lo.x);
        hl2(x1[0], x1[1], hi.y, lo.y);
        hl2(x0[2], x0[3], hi.z, lo.z);
        hl2(x1[2], x1[3], hi.w, lo.w);
        uint32_t off = (uint32_t)(kk16 * 8 + mt16) * 512 + lane * 16;
        *(uint4*)((char*)tile + off)        = hi;
        *(uint4*)((char*)tile + 8192 + off) = lo;
    }
}

// ---------------- B packs (fragment order, hi/lo), smem-staged ----------------
// chunk c: kk16=c>>8, nt16b=(c>>5)&7, lane=c&31; 16B = [b0e,b1e,b0o,b1o]
__global__ void packB3_kernel(const float* __restrict__ W_nd, const float* __restrict__ W_ed)
{
    __shared__ float ws[32][132];
    int nb = blockIdx.x, s = blockIdx.y;
    for (int e = threadIdx.x; e < 32 * 128; e += 256) {
        int k = e >> 7, n = e & 127;
        int kg = s * 32 + k, ng = nb * 128 + n;
        float v;
        if (ng < 1024) {
            v = W_nd[kg * 1024 + ng];
        } else if (ng < 2048) {
            int cc = ng - 1024;
            v = W_ed[kg * 1024 + cc] + W_ed[(2048 + kg) * 1024 + cc];
        } else {
            int cc = ng - 2048;
            v = W_ed[(1024 + kg) * 1024 + cc] - W_ed[(2048 + kg) * 1024 + cc];
        }
        ws[k][n] = v;
    }
    __syncthreads();
    __half* tile = g_BpackN + ((size_t)(nb * 32 + s)) * 8192;
    for (int c = threadIdx.x; c < 512; c += 256) {
        int kk16 = c >> 8, nt16b = (c >> 5) & 7, lane = c & 31;
        int gq = lane >> 2, tg = lane & 3;
        int kl = kk16 * 16 + 2 * tg;
        int ne = nt16b * 16 + gq, no = ne + 8;
        uint4 hi, lo;
        hl2(ws[kl][ne],     ws[kl + 1][ne], hi.x, lo.x);
        hl2(ws[kl + 8][ne], ws[kl + 9][ne], hi.y, lo.y);
        hl2(ws[kl][no],     ws[kl + 1][no], hi.z, lo.z);
        hl2(ws[kl + 8][no], ws[kl + 9][no], hi.w, lo.w);
        uint32_t off = (uint32_t)(kk16 * 8 + nt16b) * 512 + lane * 16;
        *(uint4*)((char*)tile + off)        = hi;
        *(uint4*)((char*)tile + 8192 + off) = lo;
    }
}

__global__ void packB2_kernel(const float* __restrict__ W_naf, const float* __restrict__ W_cd)
{
    __shared__ float ws[32][132];
    int nb = blockIdx.x, s = blockIdx.y;
    for (int e = threadIdx.x; e < 32 * 128; e += 256) {
        int k = e >> 7, n = e & 127;
        int kg = s * 32 + k, ng = nb * 128 + n;
        ws[k][n] = (ng < 1024) ? W_naf[kg * 1024 + ng] : W_cd[kg * 1024 + (ng - 1024)];
    }
    __syncthreads();
    __half* tile = g_BpackC + ((size_t)(nb * 32 + s)) * 8192;
    for (int c = threadIdx.x; c < 512; c += 256) {
        int kk16 = c >> 8, nt16b = (c >> 5) & 7, lane = c & 31;
        int gq = lane >> 2, tg = lane & 3;
        int kl = kk16 * 16 + 2 * tg;
        int ne = nt16b * 16 + gq, no = ne + 8;
        uint4 hi, lo;
        hl2(ws[kl][ne],     ws[kl + 1][ne], hi.x, lo.x);
        hl2(ws[kl + 8][ne], ws[kl + 9][ne], hi.y, lo.y);
        hl2(ws[kl][no],     ws[kl + 1][no], hi.z, lo.z);
        hl2(ws[kl + 8][no], ws[kl + 9][no], hi.w, lo.w);
        uint32_t off = (uint32_t)(kk16 * 8 + nt16b) * 512 + lane * 16;
        *(uint4*)((char*)tile + off)        = hi;
        *(uint4*)((char*)tile + 8192 + off) = lo;
    }
}

// ---------------- fp16 3-term GEMM, block 128x128, BK=32, 256 thr ----------------
// stage: A 16KB (hi|lo) ++ B 16KB (hi|lo) = 32KB, double buffered = 64KB
__global__ __launch_bounds__(256) void gemm3_kernel(
    const __half* __restrict__ Apack, const __half* __restrict__ Bpack,
    const float* __restrict__ bias, float* __restrict__ C, int ldc,
    const int* __restrict__ Mptr, int tanh_lo, int tanh_hi)
{
    int R = *Mptr;
    int mb = blockIdx.x, nb = blockIdx.y;
    if (mb * 128 >= R) return;
    extern __shared__ char sm[];
    uint32_t sb = smem_u32(sm);
    int tid = threadIdx.x, lane = tid & 31, w = tid >> 5;
    int gq = lane >> 2, tg = lane & 3;
    int wm = (w & 1) * 64;            // warp rows
    int wnb = (w >> 1) * 2;           // warp base nt16b (32 cols)

    const char* Ab = (const char*)Apack + (size_t)(mb * 32) * 16384;
    const char* Bb = (const char*)Bpack + (size_t)(nb * 32) * 16384;

    float acc[4][4][4];
#pragma unroll
    for (int mt = 0; mt < 4; mt++)
#pragma unroll
        for (int nt = 0; nt < 4; nt++)
#pragma unroll
            for (int q = 0; q < 4; q++) acc[mt][nt][q] = 0.f;

    // issue stage 0
    {
        uint32_t d = sb;
        const char* sa = Ab;
        const char* sbp = Bb;
#pragma unroll
        for (int i = 0; i < 4; i++) CP16(d + i * 4096 + tid * 16, sa + i * 4096 + tid * 16);
#pragma unroll
        for (int i = 0; i < 4; i++) CP16(d + 16384 + i * 4096 + tid * 16, sbp + i * 4096 + tid * 16);
        CP_COMMIT();
    }

    for (int s = 0; s < 32; s++) {
        if (s < 31) {
            uint32_t d = sb + ((s + 1) & 1) * 32768;
            const char* sa = Ab + (size_t)(s + 1) * 16384;
            const char* sbp = Bb + (size_t)(s + 1) * 16384;
#pragma unroll
            for (int i = 0; i < 4; i++) CP16(d + i * 4096 + tid * 16, sa + i * 4096 + tid * 16);
#pragma unroll
            for (int i = 0; i < 4; i++) CP16(d + 16384 + i * 4096 + tid * 16, sbp + i * 4096 + tid * 16);
            CP_COMMIT();
            CP_WAIT1();
        } else {
            CP_WAIT0();
        }
        __syncthreads();
        char* st = sm + (s & 1) * 32768;
#pragma unroll
        for (int kk = 0; kk < 2; kk++) {
            uint4 Ah[4], Al[4];
#pragma unroll
            for (int mt = 0; mt < 4; mt++) {
                uint32_t ao = (uint32_t)(kk * 8 + (w & 1) * 4 + mt) * 512 + lane * 16;
                Ah[mt] = *(const uint4*)(st + ao);
                Al[mt] = *(const uint4*)(st + 8192 + ao);
            }
#pragma unroll
            for (int ntb = 0; ntb < 2; ntb++) {
                uint32_t bo = (uint32_t)(kk * 8 + wnb + ntb) * 512 + lane * 16;
                uint4 bh = *(const uint4*)(st + 16384 + bo);
                uint4 bl = *(const uint4*)(st + 24576 + bo);
#pragma unroll
                for (int mt = 0; mt < 4; mt++) {
                    MMA16(acc[mt][2 * ntb],     Ah[mt], bh.x, bh.y);
                    MMA16(acc[mt][2 * ntb],     Al[mt], bh.x, bh.y);
                    MMA16(acc[mt][2 * ntb],     Ah[mt], bl.x, bl.y);
                    MMA16(acc[mt][2 * ntb + 1], Ah[mt], bh.z, bh.w);
                    MMA16(acc[mt][2 * ntb + 1], Al[mt], bh.z, bh.w);
                    MMA16(acc[mt][2 * ntb + 1], Ah[mt], bl.z, bl.w);
                }
            }
        }
        __syncthreads();
    }

    bool dt = (nb * 128 >= tanh_lo) && (nb * 128 < tanh_hi);
#pragma unroll
    for (int nt = 0; nt < 4; nt++) {
        int col = nb * 128 + (w >> 1) * 32 + nt * 8 + 2 * tg;
        float b0 = bias[col], b1 = bias[col + 1];
#pragma unroll
        for (int mt = 0; mt < 4; mt++) {
            int row = mb * 128 + wm + mt * 16 + gq;
            float v0 = acc[mt][nt][0] + b0;
            float v1 = acc[mt][nt][1] + b1;
            float v2 = acc[mt][nt][2] + b0;
            float v3 = acc[mt][nt][3] + b1;
            if (dt) { v0 = tanhf(v0); v1 = tanhf(v1); v2 = tanhf(v2); v3 = tanhf(v3); }
            if (row < R)     { float2 p = {v0, v1}; *(float2*)(C + (size_t)row * ldc + col) = p; }
            if (row + 8 < R) { float2 p = {v2, v3}; *(float2*)(C + (size_t)(row + 8) * ldc + col) = p; }
        }
    }
}

// ---------------- heads ----------------
__global__ void head_kernel(const float* __restrict__ W_co, const float* __restrict__ b_co,
                            const float* __restrict__ W_no, const float* __restrict__ b_no,
                            float* __restrict__ out)
{
    int blk = blockIdx.x, tid = threadIdx.x;   // 128 threads
    const float* x; const float* Wv; const float* bs; float* op;
    if (blk < 64) {
        x  = g_C2 + (size_t)blk * 2048 + 1024;
        Wv = W_co; bs = b_co; op = out + blk * 2;
    } else {
        int r = blk - 64;
        int b = r / 26, m = r - b * 26;
        op = out + 128 + r * 2;
        if (m > g_count[b]) {          // zero node row -> constant logits
            if (tid == 0) { op[0] = g_zlog[0]; op[1] = g_zlog[1]; }
            return;
        }
        x  = g_Cbig + (size_t)(g_pref[b] + m) * 3072;
        Wv = W_no; bs = b_no;
    }
    float xs[8], ws[16];
    {
        const float4* xv = (const float4*)(x + tid * 8);
        *(float4*)xs       = xv[0];
        *(float4*)(xs + 4) = xv[1];
        const float4* wv = (const float4*)(Wv + tid * 16);
#pragma unroll
        for (int q = 0; q < 4; q++) *(float4*)(ws + q * 4) = wv[q];
    }
    float a0 = 0.f, a1 = 0.f;
#pragma unroll
    for (int hh = 0; hh < 8; hh++) {
        a0 = fmaf(xs[hh], ws[2 * hh], a0);
        a1 = fmaf(xs[hh], ws[2 * hh + 1], a1);
    }
#pragma unroll
    for (int o = 16; o > 0; o >>= 1) {
        a0 += __shfl_down_sync(0xffffffffu, a0, o);
        a1 += __shfl_down_sync(0xffffffffu, a1, o);
    }
    __shared__ float s0[4], s1[4];
    int wid = tid >> 5, lane = tid & 31;
    if (lane == 0) { s0[wid] = a0; s1[wid] = a1; }
    __syncthreads();
    if (tid == 0) {
        op[0] = s0[0] + s0[1] + s0[2] + s0[3] + bs[0];
        op[1] = s1[0] + s1[1] + s1[2] + s1[3] + bs[1];
    }
}

// ---------------- edge logits ----------------
__global__ void edge_kernel(const float* __restrict__ W_eo, const float* __restrict__ b_eo,
                            const float* __restrict__ b_ed, float* __restrict__ out)
{
    int ke = blockIdx.x;
    int b  = ke / 676;
    int k  = ke - b * 676;
    int n  = g_count[b] + 1;
    int tid = threadIdx.x;   // 128

    float xs[8];
    if (k < n * n) {
        int i = k / n, j = k - i * n;
        int pj = g_pref[b] + j, pi = g_pref[b] + i;
        const float* U = g_Cbig + (size_t)pj * 3072 + 1024 + tid * 8;
        const float* V = g_Cbig + (size_t)pi * 3072 + 2048 + tid * 8;
        float us[8], vs[8];
        *(float4*)us       = ((const float4*)U)[0];
        *(float4*)(us + 4) = ((const float4*)U)[1];
        *(float4*)vs       = ((const float4*)V)[0];
        *(float4*)(vs + 4) = ((const float4*)V)[1];
#pragma unroll
        for (int hh = 0; hh < 8; hh++) xs[hh] = tanhf(us[hh] + vs[hh]);
    } else {
        const float* be = b_ed + tid * 8;
        float bs8[8];
        *(float4*)bs8       = ((const float4*)be)[0];
        *(float4*)(bs8 + 4) = ((const float4*)be)[1];
#pragma unroll
        for (int hh = 0; hh < 8; hh++) xs[hh] = tanhf(bs8[hh]);
    }
    float ws[16];
    {
        const float4* wv = (const float4*)(W_eo + tid * 16);
#pragma unroll
        for (int q = 0; q < 4; q++) *(float4*)(ws + q * 4) = wv[q];
    }
    float a0 = 0.f, a1 = 0.f;
#pragma unroll
    for (int hh = 0; hh < 8; hh++) {
        a0 = fmaf(xs[hh], ws[2 * hh], a0);
        a1 = fmaf(xs[hh], ws[2 * hh + 1], a1);
    }
#pragma unroll
    for (int o = 16; o > 0; o >>= 1) {
        a0 += __shfl_down_sync(0xffffffffu, a0, o);
        a1 += __shfl_down_sync(0xffffffffu, a1, o);
    }
    __shared__ float s0[4], s1[4];
    int wid = tid >> 5, lane = tid & 31;
    if (lane == 0) { s0[wid] = a0; s1[wid] = a1; }
    __syncthreads();
    if (tid == 0) {
        float* op = out + 3456 + (size_t)ke * 2;
        op[0] = s0[0] + s0[1] + s0[2] + s0[3] + b_eo[0];
        op[1] = s1[0] + s1[1] + s1[2] + s1[3] + b_eo[1];
    }
}

// ---------------- launch ----------------
extern "C" void kernel_launch(void* const* d_in, const int* in_sizes, int n_in,
                              void* d_out, int out_size)
{
    const float* seq   = (const float*)d_in[0];
    const int*   off   = (const int*)d_in[1];
    const float* W_naf = (const float*)d_in[4];
    const float* b_naf = (const float*)d_in[5];
    const float* W_cd  = (const float*)d_in[6];
    const float* b_cd  = (const float*)d_in[7];
    const float* W_co  = (const float*)d_in[8];
    const float* b_co  = (const float*)d_in[9];
    const float* W_nd  = (const float*)d_in[10];
    const float* b_nd  = (const float*)d_in[11];
    const float* W_no  = (const float*)d_in[12];
    const float* b_no  = (const float*)d_in[13];
    const float* W_ed  = (const float*)d_in[14];
    const float* b_ed  = (const float*)d_in[15];
    const float* W_eo  = (const float*)d_in[16];
    const float* b_eo  = (const float*)d_in[17];
    float* out = (float*)d_out;

    float *pbcat2, *pbcat3, *pC2, *pCbig;
    __half *pApN, *pApC, *pBpN, *pBpC;
    int *pR, *pM1;
    cudaGetSymbolAddress((void**)&pbcat2, g_bcat2);
    cudaGetSymbolAddress((void**)&pbcat3, g_bcat3);
    cudaGetSymbolAddress((void**)&pC2,    g_C2);
    cudaGetSymbolAddress((void**)&pCbig,  g_Cbig);
    cudaGetSymbolAddress((void**)&pApN,   g_ApackN);
    cudaGetSymbolAddress((void**)&pApC,   g_ApackC);
    cudaGetSymbolAddress((void**)&pBpN,   g_BpackN);
    cudaGetSymbolAddress((void**)&pBpC,   g_BpackC);
    cudaGetSymbolAddress((void**)&pR,     g_R);
    cudaGetSymbolAddress((void**)&pM1,    g_M1);

    cudaFuncSetAttribute(gemm3_kernel, cudaFuncAttributeMaxDynamicSharedMemorySize, 65536);

    // weight-only prep
    prep_bias_kernel<<<12, 256>>>(b_naf, b_cd, b_nd, b_ed);
    zlog_kernel<<<1, 128>>>(b_nd, W_no, b_no);
    packB3_kernel<<<dim3(24, 32), 256>>>(W_nd, W_ed);
    packB2_kernel<<<dim3(16, 32), 256>>>(W_naf, W_cd);
    // data path
    seg_kernel<<<dim3(64, 26), 256>>>(seq, off);
    prefix_kernel<<<1, 256>>>();
    packAcls_kernel<<<32, 256>>>(seq);
    // G1: cls @ [W_naf | W_cd] -> g_C2 (tanh on cols [1024,2048))
    gemm3_kernel<<<dim3(1, 16), 256, 65536>>>(pApC, pBpC, pbcat2, pC2, 2048, pM1, 1024, 2048);
    scatter_naf_kernel<<<64, 256>>>();
    packAnode_kernel<<<dim3(13, 32), 256>>>();
    // G2: nodeC @ [W_nd | W1+W3 | W2-W3] -> g_Cbig (tanh on cols [0,1024))
    gemm3_kernel<<<dim3(13, 24), 256, 65536>>>(pApN, pBpN, pbcat3, pCbig, 3072, pR, 0, 1024);
    // heads
    head_kernel<<<64 + 1664, 128>>>(W_co, b_co, W_no, b_no, out);
    edge_kernel<<<64 * 676, 128>>>(W_eo, b_eo, b_ed, out);
}

// round 5
// speedup vs baseline: 2.7665x; 1.0094x over previous
#include <cuda_runtime.h>
#include <cuda_fp16.h>
#include <math.h>
#include <stdint.h>

// Shapes (fixed): B=64, S=512, H=1024, M=26, E=676
// Output: logits(64,2) ++ node_logits(64,26,2) ++ edge_logits(64,676,2) = 89984 f32
//
// GEMMs via legacy mma.m16n8k16.f16 with 3-term hi/lo split (fp32-class accuracy):
//  G1: cls(64x1024)   @ [W_naf|W_cd](1024x2048)          -> g_C2
//  G2: nodeC(Rx1024)  @ [W_nd|W1+W3|W2-W3](1024x3072)    -> g_Cbig (compact rows)
// Block tile 128x128, K slabs of 32, pre-fragmented packs, cp.async double buffer.

// ---------------- scratch ----------------
__device__ float g_bcat2[2048];
__device__ float g_bcat3[3072];
__device__ float g_node[64 * 26 * 1024];
__device__ float g_C2[64 * 2048];
__device__ float g_Cbig[1664 * 3072];    // compact rows used: [T_nd | U | V]
__device__ int   g_count[64];
__device__ int   g_pref[64];
__device__ int   g_rowmap[1664];
__device__ int   g_R;
__device__ int   g_M1 = 64;
__device__ float g_zlog[2];

// pre-fragmented fp16 hi/lo packs (slab = 128rows x 32k, hi 8KB + lo 8KB = 8192 halves)
__device__ __align__(16) __half g_ApackN[13 * 32 * 8192];
__device__ __align__(16) __half g_ApackC[32 * 8192];
__device__ __align__(16) __half g_BpackN[24 * 32 * 8192];
__device__ __align__(16) __half g_BpackC[16 * 32 * 8192];

// ---------------- helpers ----------------
__device__ __forceinline__ uint32_t smem_u32(const void* p) {
    uint32_t a;
    asm("{ .reg .u64 t; cvta.to.shared.u64 t, %1; cvt.u32.u64 %0, t; }" : "=r"(a) : "l"(p));
    return a;
}
#define CP16(dst, src) asm volatile("cp.async.cg.shared.global [%0], [%1], 16;" :: "r"(dst), "l"(src) : "memory")
#define CP_COMMIT()    asm volatile("cp.async.commit_group;" ::: "memory")
#define CP_WAIT1()     asm volatile("cp.async.wait_group 1;" ::: "memory")
#define CP_WAIT0()     asm volatile("cp.async.wait_group 0;" ::: "memory")

#define MMA16(d, a, bb0, bb1) \
    asm volatile("mma.sync.aligned.m16n8k16.row.col.f32.f16.f16.f32 " \
                 "{%0,%1,%2,%3}, {%4,%5,%6,%7}, {%8,%9}, {%0,%1,%2,%3};" \
                 : "+f"((d)[0]), "+f"((d)[1]), "+f"((d)[2]), "+f"((d)[3]) \
                 : "r"((a).x), "r"((a).y), "r"((a).z), "r"((a).w), "r"(bb0), "r"(bb1))

// hi/lo fp16 split of a float pair -> packed half2 regs
__device__ __forceinline__ void hl2(float a, float b, uint32_t& h, uint32_t& l) {
    __half ha = __float2half_rn(a), hb = __float2half_rn(b);
    __half la = __float2half_rn(a - __half2float(ha));
    __half lb = __float2half_rn(b - __half2float(hb));
    __half2 H = __halves2half2(ha, hb), L = __halves2half2(la, lb);
    h = *(uint32_t*)&H; l = *(uint32_t*)&L;
}

// ---------------- K0: biases ----------------
__global__ void prep_bias_kernel(const float* __restrict__ b_naf, const float* __restrict__ b_cd,
                                 const float* __restrict__ b_nd,  const float* __restrict__ b_ed)
{
    int t = blockIdx.x * blockDim.x + threadIdx.x;
    if (t < 2048) g_bcat2[t] = (t < 1024) ? b_naf[t] : b_cd[t - 1024];
    if (t < 3072) g_bcat3[t] = (t < 1024) ? b_nd[t] : ((t < 2048) ? b_ed[t - 1024] : 0.0f);
}

// zero-row node logits: tanh(b_nd) @ W_no + b_no
__global__ void zlog_kernel(const float* __restrict__ b_nd, const float* __restrict__ W_no,
                            const float* __restrict__ b_no)
{
    int tid = threadIdx.x;  // 128
    float a0 = 0.f, a1 = 0.f;
#pragma unroll
    for (int hh = 0; hh < 8; hh++) {
        float x = tanhf(b_nd[tid * 8 + hh]);
        a0 = fmaf(x, W_no[(tid * 8 + hh) * 2],     a0);
        a1 = fmaf(x, W_no[(tid * 8 + hh) * 2 + 1], a1);
    }
#pragma unroll
    for (int o = 16; o > 0; o >>= 1) {
        a0 += __shfl_down_sync(0xffffffffu, a0, o);
        a1 += __shfl_down_sync(0xffffffffu, a1, o);
    }
    __shared__ float s0[4], s1[4];
    int wid = tid >> 5, lane = tid & 31;
    if (lane == 0) { s0[wid] = a0; s1[wid] = a1; }
    __syncthreads();
    if (tid == 0) {
        g_zlog[0] = s0[0] + s0[1] + s0[2] + s0[3] + b_no[0];
        g_zlog[1] = s1[0] + s1[1] + s1[2] + s1[3] + b_no[1];
    }
}

// ---------------- K1: segment means + counts ----------------
__global__ void seg_kernel(const float* __restrict__ seq, const int* __restrict__ off)
{
    int b = blockIdx.x, m = blockIdx.y;
    __shared__ int soff[25];
    int tid = threadIdx.x;
    if (tid < 25) soff[tid] = off[b * 25 + tid];
    __syncthreads();
    int c = 0;
#pragma unroll
    for (int q = 0; q < 25; q++) c += (soff[q] > 0);
    if (m == 0 && tid == 0) g_count[b] = c;

    float* dst = g_node + ((size_t)b * 26 + m) * 1024 + tid * 4;
    if (m >= c) { float4 z = {0.f, 0.f, 0.f, 0.f}; *(float4*)dst = z; return; }
    int e  = soff[m];
    int s0 = (m ? soff[m - 1] : 0) + 1;
    int len = e - s0 + 1;
    const float* p = seq + ((size_t)b * 512 + s0) * 1024 + tid * 4;
    float4 acc = {0.f, 0.f, 0.f, 0.f};
#pragma unroll 4
    for (int s = 0; s < len; s++) {
        float4 v = *(const float4*)(p + (size_t)s * 1024);
        acc.x += v.x; acc.y += v.y; acc.z += v.z; acc.w += v.w;
    }
    float inv = 1.0f / (float)len;
    float4 r = {acc.x * inv, acc.y * inv, acc.z * inv, acc.w * inv};
    *(float4*)dst = r;
}

// ---------------- prefix + rowmap ----------------
__global__ void prefix_kernel()
{
    __shared__ int sc[64], sp[64];
    int tid = threadIdx.x;
    if (tid < 64) sc[tid] = g_count[tid];
    __syncthreads();
    if (tid == 0) {
        int p = 0;
        for (int b = 0; b < 64; b++) { sp[b] = p; g_pref[b] = p; p += sc[b] + 1; }
        g_R = p;
    }
    __syncthreads();
    for (int r = tid; r < 1664; r += 256) {
        int b = r / 26, m = r - b * 26;
        if (m <= sc[b]) g_rowmap[sp[b] + m] = r;
    }
}

// ---------------- K3: node_full[b, count[b], :] += naf ----------------
__global__ void scatter_naf_kernel()
{
    int b = blockIdx.x, tid = threadIdx.x;
    int c = g_count[b];
    float* dst = g_node + ((size_t)b * 26 + c) * 1024 + tid * 4;
    const float* naf = g_C2 + (size_t)b * 2048 + tid * 4;
    float4 d = *(float4*)dst;
    float4 n = *(const float4*)naf;
    d.x += n.x; d.y += n.y; d.z += n.z; d.w += n.w;
    *(float4*)dst = d;
}

// ---------------- A packs (fragment order, hi/lo) ----------------
// chunk c: kk16=c>>8, mt16=(c>>5)&7, lane=c&31; 16B = [a0pair,a1pair,a2pair,a3pair]
__global__ void packAnode_kernel()
{
    int mb = blockIdx.x, s = blockIdx.y;
    int R = g_R;
    if (mb * 128 >= R) return;
    __half* tile = g_ApackN + ((size_t)(mb * 32 + s)) * 8192;
    for (int c = threadIdx.x; c < 512; c += 256) {
        int kk16 = c >> 8, mt16 = (c >> 5) & 7, lane = c & 31;
        int gq = lane >> 2, tg = lane & 3;
        int kb = s * 32 + kk16 * 16 + 2 * tg;
        int r0 = mb * 128 + mt16 * 16 + gq, r1 = r0 + 8;
        float x0[4] = {0,0,0,0}, x1[4] = {0,0,0,0};
        if (r0 < R) { const float* p = g_node + (size_t)g_rowmap[r0] * 1024 + kb;
                      x0[0]=p[0]; x0[1]=p[1]; x0[2]=p[8]; x0[3]=p[9]; }
        if (r1 < R) { const float* p = g_node + (size_t)g_rowmap[r1] * 1024 + kb;
                      x1[0]=p[0]; x1[1]=p[1]; x1[2]=p[8]; x1[3]=p[9]; }
        uint4 hi, lo;
        hl2(x0[0], x0[1], hi.x, lo.x);
        hl2(x1[0], x1[1], hi.y, lo.y);
        hl2(x0[2], x0[3], hi.z, lo.z);
        hl2(x1[2], x1[3], hi.w, lo.w);
        uint32_t off = (uint32_t)(kk16 * 8 + mt16) * 512 + lane * 16;
        *(uint4*)((char*)tile + off)        = hi;
        *(uint4*)((char*)tile + 8192 + off) = lo;
    }
}

__global__ void packAcls_kernel(const float* __restrict__ seq)
{
    int s = blockIdx.x;
    __half* tile = g_ApackC + ((size_t)s) * 8192;
    for (int c = threadIdx.x; c < 512; c += 256) {
        int kk16 = c >> 8, mt16 = (c >> 5) & 7, lane = c & 31;
        int gq = lane >> 2, tg = lane & 3;
        int kb = s * 32 + kk16 * 16 + 2 * tg;
        int r0 = mt16 * 16 + gq, r1 = r0 + 8;
        float x0[4] = {0,0,0,0}, x1[4] = {0,0,0,0};
        if (r0 < 64) { const float* p = seq + (size_t)r0 * 524288 + kb;
                       x0[0]=p[0]; x0[1]=p[1]; x0[2]=p[8]; x0[3]=p[9]; }
        if (r1 < 64) { const float* p = seq + (size_t)r1 * 524288 + kb;
                       x1[0]=p[0]; x1[1]=p[1]; x1[2]=p[8]; x1[3]=p[9]; }
        uint4 hi, lo;
        hl2(x0[0], x0[1], hi.x, lo.x);
        hl2(x1[0], x1[1], hi.y, lo.y);
        hl2(x0[2], x0[3], hi.z, lo.z);
        hl2(x1[2], x1[3], hi.w, lo.w);
        uint32_t off = (uint32_t)(kk16 * 8 + mt16) * 512 + lane * 16;
        *(uint4*)((char*)tile + off)        = hi;
        *(uint4*)((char*)tile + 8192 + off) = lo;
    }
}

// ---------------- B packs (fragment order, hi/lo), smem-staged ----------------
// chunk c: kk16=c>>8, nt16b=(c>>5)&7, lane=c&31; 16B = [b0e,b1e,b0o,b1o]
__global__ void packB3_kernel(const float* __restrict__ W_nd, const float* __restrict__ W_ed)
{
    __shared__ float ws[32][132];
    int nb = blockIdx.x, s = blockIdx.y;
    for (int e = threadIdx.x; e < 32 * 128; e += 256) {
        int k = e >> 7, n = e & 127;
        int kg = s * 32 + k, ng = nb * 128 + n;
        float v;
        if (ng < 1024) {
            v = W_nd[kg * 1024 + ng];
        } else if (ng < 2048) {
            int cc = ng - 1024;
            v = W_ed[kg * 1024 + cc] + W_ed[(2048 + kg) * 1024 + cc];
        } else {
            int cc = ng - 2048;
            v = W_ed[(1024 + kg) * 1024 + cc] - W_ed[(2048 + kg) * 1024 + cc];
        }
        ws[k][n] = v;
    }
    __syncthreads();
    __half* tile = g_BpackN + ((size_t)(nb * 32 + s)) * 8192;
    for (int c = threadIdx.x; c < 512; c += 256) {
        int kk16 = c >> 8, nt16b = (c >> 5) & 7, lane = c & 31;
        int gq = lane >> 2, tg = lane & 3;
        int kl = kk16 * 16 + 2 * tg;
        int ne = nt16b * 16 + gq, no = ne + 8;
        uint4 hi, lo;
        hl2(ws[kl][ne],     ws[kl + 1][ne], hi.x, lo.x);
        hl2(ws[kl + 8][ne], ws[kl + 9][ne], hi.y, lo.y);
        hl2(ws[kl][no],     ws[kl + 1][no], hi.z, lo.z);
        hl2(ws[kl + 8][no], ws[kl + 9][no], hi.w, lo.w);
        uint32_t off = (uint32_t)(kk16 * 8 + nt16b) * 512 + lane * 16;
        *(uint4*)((char*)tile + off)        = hi;
        *(uint4*)((char*)tile + 8192 + off) = lo;
    }
}

__global__ void packB2_kernel(const float* __restrict__ W_naf, const float* __restrict__ W_cd)
{
    __shared__ float ws[32][132];
    int nb = blockIdx.x, s = blockIdx.y;
    for (int e = threadIdx.x; e < 32 * 128; e += 256) {
        int k = e >> 7, n = e & 127;
        int kg = s * 32 + k, ng = nb * 128 + n;
        ws[k][n] = (ng < 1024) ? W_naf[kg * 1024 + ng] : W_cd[kg * 1024 + (ng - 1024)];
    }
    __syncthreads();
    __half* tile = g_BpackC + ((size_t)(nb * 32 + s)) * 8192;
    for (int c = threadIdx.x; c < 512; c += 256) {
        int kk16 = c >> 8, nt16b = (c >> 5) & 7, lane = c & 31;
        int gq = lane >> 2, tg = lane & 3;
        int kl = kk16 * 16 + 2 * tg;
        int ne = nt16b * 16 + gq, no = ne + 8;
        uint4 hi, lo;
        hl2(ws[kl][ne],     ws[kl + 1][ne], hi.x, lo.x);
        hl2(ws[kl + 8][ne], ws[kl + 9][ne], hi.y, lo.y);
        hl2(ws[kl][no],     ws[kl + 1][no], hi.z, lo.z);
        hl2(ws[kl + 8][no], ws[kl + 9][no], hi.w, lo.w);
        uint32_t off = (uint32_t)(kk16 * 8 + nt16b) * 512 + lane * 16;
        *(uint4*)((char*)tile + off)        = hi;
        *(uint4*)((char*)tile + 8192 + off) = lo;
    }
}

// ---------------- fp16 3-term GEMM, block 128x128, BK=32, 256 thr ----------------
// stage: A 16KB (hi|lo) ++ B 16KB (hi|lo) = 32KB, double buffered = 64KB
__global__ __launch_bounds__(256) void gemm3_kernel(
    const __half* __restrict__ Apack, const __half* __restrict__ Bpack,
    const float* __restrict__ bias, float* __restrict__ C, int ldc,
    const int* __restrict__ Mptr, int tanh_lo, int tanh_hi)
{
    int R = *Mptr;
    int mb = blockIdx.x, nb = blockIdx.y;
    if (mb * 128 >= R) return;
    extern __shared__ char sm[];
    uint32_t sb = smem_u32(sm);
    int tid = threadIdx.x, lane = tid & 31, w = tid >> 5;
    int gq = lane >> 2, tg = lane & 3;
    int wm = (w & 1) * 64;            // warp rows
    int wnb = (w >> 1) * 2;           // warp base nt16b (32 cols)

    const char* Ab = (const char*)Apack + (size_t)(mb * 32) * 16384;
    const char* Bb = (const char*)Bpack + (size_t)(nb * 32) * 16384;

    float acc[4][4][4];
#pragma unroll
    for (int mt = 0; mt < 4; mt++)
#pragma unroll
        for (int nt = 0; nt < 4; nt++)
#pragma unroll
            for (int q = 0; q < 4; q++) acc[mt][nt][q] = 0.f;

    // issue stage 0
    {
        uint32_t d = sb;
        const char* sa = Ab;
        const char* sbp = Bb;
#pragma unroll
        for (int i = 0; i < 4; i++) CP16(d + i * 4096 + tid * 16, sa + i * 4096 + tid * 16);
#pragma unroll
        for (int i = 0; i < 4; i++) CP16(d + 16384 + i * 4096 + tid * 16, sbp + i * 4096 + tid * 16);
        CP_COMMIT();
    }

    for (int s = 0; s < 32; s++) {
        if (s < 31) {
            uint32_t d = sb + ((s + 1) & 1) * 32768;
            const char* sa = Ab + (size_t)(s + 1) * 16384;
            const char* sbp = Bb + (size_t)(s + 1) * 16384;
#pragma unroll
            for (int i = 0; i < 4; i++) CP16(d + i * 4096 + tid * 16, sa + i * 4096 + tid * 16);
#pragma unroll
            for (int i = 0; i < 4; i++) CP16(d + 16384 + i * 4096 + tid * 16, sbp + i * 4096 + tid * 16);
            CP_COMMIT();
            CP_WAIT1();
        } else {
            CP_WAIT0();
        }
        __syncthreads();
        char* st = sm + (s & 1) * 32768;
#pragma unroll
        for (int kk = 0; kk < 2; kk++) {
            uint4 Ah[4], Al[4];
#pragma unroll
            for (int mt = 0; mt < 4; mt++) {
                uint32_t ao = (uint32_t)(kk * 8 + (w & 1) * 4 + mt) * 512 + lane * 16;
                Ah[mt] = *(const uint4*)(st + ao);
                Al[mt] = *(const uint4*)(st + 8192 + ao);
            }
#pragma unroll
            for (int ntb = 0; ntb < 2; ntb++) {
                uint32_t bo = (uint32_t)(kk * 8 + wnb + ntb) * 512 + lane * 16;
                uint4 bh = *(const uint4*)(st + 16384 + bo);
                uint4 bl = *(const uint4*)(st + 24576 + bo);
#pragma unroll
                for (int mt = 0; mt < 4; mt++) {
                    MMA16(acc[mt][2 * ntb],     Ah[mt], bh.x, bh.y);
                    MMA16(acc[mt][2 * ntb],     Al[mt], bh.x, bh.y);
                    MMA16(acc[mt][2 * ntb],     Ah[mt], bl.x, bl.y);
                    MMA16(acc[mt][2 * ntb + 1], Ah[mt], bh.z, bh.w);
                    MMA16(acc[mt][2 * ntb + 1], Al[mt], bh.z, bh.w);
                    MMA16(acc[mt][2 * ntb + 1], Ah[mt], bl.z, bl.w);
                }
            }
        }
        __syncthreads();
    }

    bool dt = (nb * 128 >= tanh_lo) && (nb * 128 < tanh_hi);
#pragma unroll
    for (int nt = 0; nt < 4; nt++) {
        int col = nb * 128 + (w >> 1) * 32 + nt * 8 + 2 * tg;
        float b0 = bias[col], b1 = bias[col + 1];
#pragma unroll
        for (int mt = 0; mt < 4; mt++) {
            int row = mb * 128 + wm + mt * 16 + gq;
            float v0 = acc[mt][nt][0] + b0;
            float v1 = acc[mt][nt][1] + b1;
            float v2 = acc[mt][nt][2] + b0;
            float v3 = acc[mt][nt][3] + b1;
            if (dt) { v0 = tanhf(v0); v1 = tanhf(v1); v2 = tanhf(v2); v3 = tanhf(v3); }
            if (row < R)     { float2 p = {v0, v1}; *(float2*)(C + (size_t)row * ldc + col) = p; }
            if (row + 8 < R) { float2 p = {v2, v3}; *(float2*)(C + (size_t)(row + 8) * ldc + col) = p; }
        }
    }
}

// ---------------- heads ----------------
__global__ void head_kernel(const float* __restrict__ W_co, const float* __restrict__ b_co,
                            const float* __restrict__ W_no, const float* __restrict__ b_no,
                            float* __restrict__ out)
{
    int blk = blockIdx.x, tid = threadIdx.x;   // 128 threads
    const float* x; const float* Wv; const float* bs; float* op;
    if (blk < 64) {
        x  = g_C2 + (size_t)blk * 2048 + 1024;
        Wv = W_co; bs = b_co; op = out + blk * 2;
    } else {
        int r = blk - 64;
        int b = r / 26, m = r - b * 26;
        op = out + 128 + r * 2;
        if (m > g_count[b]) {          // zero node row -> constant logits
            if (tid == 0) { op[0] = g_zlog[0]; op[1] = g_zlog[1]; }
            return;
        }
        x  = g_Cbig + (size_t)(g_pref[b] + m) * 3072;
        Wv = W_no; bs = b_no;
    }
    float xs[8], ws[16];
    {
        const float4* xv = (const float4*)(x + tid * 8);
        *(float4*)xs       = xv[0];
        *(float4*)(xs + 4) = xv[1];
        const float4* wv = (const float4*)(Wv + tid * 16);
#pragma unroll
        for (int q = 0; q < 4; q++) *(float4*)(ws + q * 4) = wv[q];
    }
    float a0 = 0.f, a1 = 0.f;
#pragma unroll
    for (int hh = 0; hh < 8; hh++) {
        a0 = fmaf(xs[hh], ws[2 * hh], a0);
        a1 = fmaf(xs[hh], ws[2 * hh + 1], a1);
    }
#pragma unroll
    for (int o = 16; o > 0; o >>= 1) {
        a0 += __shfl_down_sync(0xffffffffu, a0, o);
        a1 += __shfl_down_sync(0xffffffffu, a1, o);
    }
    __shared__ float s0[4], s1[4];
    int wid = tid >> 5, lane = tid & 31;
    if (lane == 0) { s0[wid] = a0; s1[wid] = a1; }
    __syncthreads();
    if (tid == 0) {
        op[0] = s0[0] + s0[1] + s0[2] + s0[3] + bs[0];
        op[1] = s1[0] + s1[1] + s1[2] + s1[3] + bs[1];
    }
}

// ---------------- edge logits ----------------
__global__ void edge_kernel(const float* __restrict__ W_eo, const float* __restrict__ b_eo,
                            const float* __restrict__ b_ed, float* __restrict__ out)
{
    int ke = blockIdx.x;
    int b  = ke / 676;
    int k  = ke - b * 676;
    int n  = g_count[b] + 1;
    int tid = threadIdx.x;   // 128

    float xs[8];
    if (k < n * n) {
        int i = k / n, j = k - i * n;
        int pj = g_pref[b] + j, pi = g_pref[b] + i;
        const float* U = g_Cbig + (size_t)pj * 3072 + 1024 + tid * 8;
        const float* V = g_Cbig + (size_t)pi * 3072 + 2048 + tid * 8;
        float us[8], vs[8];
        *(float4*)us       = ((const float4*)U)[0];
        *(float4*)(us + 4) = ((const float4*)U)[1];
        *(float4*)vs       = ((const float4*)V)[0];
        *(float4*)(vs + 4) = ((const float4*)V)[1];
#pragma unroll
        for (int hh = 0; hh < 8; hh++) xs[hh] = tanhf(us[hh] + vs[hh]);
    } else {
        const float* be = b_ed + tid * 8;
        float bs8[8];
        *(float4*)bs8       = ((const float4*)be)[0];
        *(float4*)(bs8 + 4) = ((const float4*)be)[1];
#pragma unroll
        for (int hh = 0; hh < 8; hh++) xs[hh] = tanhf(bs8[hh]);
    }
    float ws[16];
    {
        const float4* wv = (const float4*)(W_eo + tid * 16);
#pragma unroll
        for (int q = 0; q < 4; q++) *(float4*)(ws + q * 4) = wv[q];
    }
    float a0 = 0.f, a1 = 0.f;
#pragma unroll
    for (int hh = 0; hh < 8; hh++) {
        a0 = fmaf(xs[hh], ws[2 * hh], a0);
        a1 = fmaf(xs[hh], ws[2 * hh + 1], a1);
    }
#pragma unroll
    for (int o = 16; o > 0; o >>= 1) {
        a0 += __shfl_down_sync(0xffffffffu, a0, o);
        a1 += __shfl_down_sync(0xffffffffu, a1, o);
    }
    __shared__ float s0[4], s1[4];
    int wid = tid >> 5, lane = tid & 31;
    if (lane == 0) { s0[wid] = a0; s1[wid] = a1; }
    __syncthreads();
    if (tid == 0) {
        float* op = out + 3456 + (size_t)ke * 2;
        op[0] = s0[0] + s0[1] + s0[2] + s0[3] + b_eo[0];
        op[1] = s1[0] + s1[1] + s1[2] + s1[3] + b_eo[1];
    }
}

// ---------------- launch ----------------
extern "C" void kernel_launch(void* const* d_in, const int* in_sizes, int n_in,
                              void* d_out, int out_size)
{
    const float* seq   = (const float*)d_in[0];
    const int*   off   = (const int*)d_in[1];
    const float* W_naf = (const float*)d_in[4];
    const float* b_naf = (const float*)d_in[5];
    const float* W_cd  = (const float*)d_in[6];
    const float* b_cd  = (const float*)d_in[7];
    const float* W_co  = (const float*)d_in[8];
    const float* b_co  = (const float*)d_in[9];
    const float* W_nd  = (const float*)d_in[10];
    const float* b_nd  = (const float*)d_in[11];
    const float* W_no  = (const float*)d_in[12];
    const float* b_no  = (const float*)d_in[13];
    const float* W_ed  = (const float*)d_in[14];
    const float* b_ed  = (const float*)d_in[15];
    const float* W_eo  = (const float*)d_in[16];
    const float* b_eo  = (const float*)d_in[17];
    float* out = (float*)d_out;

    float *pbcat2, *pbcat3, *pC2, *pCbig;
    __half *pApN, *pApC, *pBpN, *pBpC;
    int *pR, *pM1;
    cudaGetSymbolAddress((void**)&pbcat2, g_bcat2);
    cudaGetSymbolAddress((void**)&pbcat3, g_bcat3);
    cudaGetSymbolAddress((void**)&pC2,    g_C2);
    cudaGetSymbolAddress((void**)&pCbig,  g_Cbig);
    cudaGetSymbolAddress((void**)&pApN,   g_ApackN);
    cudaGetSymbolAddress((void**)&pApC,   g_ApackC);
    cudaGetSymbolAddress((void**)&pBpN,   g_BpackN);
    cudaGetSymbolAddress((void**)&pBpC,   g_BpackC);
    cudaGetSymbolAddress((void**)&pR,     g_R);
    cudaGetSymbolAddress((void**)&pM1,    g_M1);

    cudaFuncSetAttribute(gemm3_kernel, cudaFuncAttributeMaxDynamicSharedMemorySize, 65536);

    // weight-only prep
    prep_bias_kernel<<<12, 256>>>(b_naf, b_cd, b_nd, b_ed);
    zlog_kernel<<<1, 128>>>(b_nd, W_no, b_no);
    packB3_kernel<<<dim3(24, 32), 256>>>(W_nd, W_ed);
    packB2_kernel<<<dim3(16, 32), 256>>>(W_naf, W_cd);
    // data path
    seg_kernel<<<dim3(64, 26), 256>>>(seq, off);
    prefix_kernel<<<1, 256>>>();
    packAcls_kernel<<<32, 256>>>(seq);
    // G1: cls @ [W_naf | W_cd] -> g_C2 (tanh on cols [1024,2048))
    gemm3_kernel<<<dim3(1, 16), 256, 65536>>>(pApC, pBpC, pbcat2, pC2, 2048, pM1, 1024, 2048);
    scatter_naf_kernel<<<64, 256>>>();
    packAnode_kernel<<<dim3(13, 32), 256>>>();
    // G2: nodeC @ [W_nd | W1+W3 | W2-W3] -> g_Cbig (tanh on cols [0,1024))
    gemm3_kernel<<<dim3(13, 24), 256, 65536>>>(pApN, pBpN, pbcat3, pCbig, 3072, pR, 0, 1024);
    // heads
    head_kernel<<<64 + 1664, 128>>>(W_co, b_co, W_no, b_no, out);
    edge_kernel<<<64 * 676, 128>>>(W_eo, b_eo, b_ed, out);
}